// round 17
// baseline (speedup 1.0000x reference)
#include <cuda_runtime.h>
#include <cuda_bf16.h>
#include <math.h>
#include <stdint.h>

#define BATCH 8
#define LEN   1024
#define DIN   512
#define NHEAD 8
#define HDIM  64
#define HD    512   // NHEAD*HDIM

// --- device-global scratch (no allocation allowed) ---
__device__ uint16_t g_wsp[3*2*DIN*HD];          // [z][split][n][k] bf16
__device__ uint16_t g_xsp[3*2*BATCH*LEN*DIN];   // [z][split][m][k] bf16
#define PLANE_U32 (64*1024*32)
__device__ uint32_t g_qs[2*PLANE_U32];
__device__ uint32_t g_ks[2*PLANE_U32];
__device__ uint32_t g_vs[2*PLANE_U32];

// ===========================================================================
// helpers
// ===========================================================================
__device__ __forceinline__ uint32_t smem_u32(const void* p) {
    uint32_t a;
    asm("{ .reg .u64 t; cvta.to.shared.u64 t, %1; cvt.u32.u64 %0, t; }" : "=r"(a) : "l"(p));
    return a;
}
__device__ __forceinline__ void ldsm_x4(uint32_t* r, uint32_t addr) {
    asm volatile("ldmatrix.sync.aligned.m8n8.x4.shared.b16 {%0,%1,%2,%3}, [%4];"
                 : "=r"(r[0]), "=r"(r[1]), "=r"(r[2]), "=r"(r[3]) : "r"(addr));
}
__device__ __forceinline__ void ldsm_x4_t(uint32_t* r, uint32_t addr) {
    asm volatile("ldmatrix.sync.aligned.m8n8.x4.trans.shared.b16 {%0,%1,%2,%3}, [%4];"
                 : "=r"(r[0]), "=r"(r[1]), "=r"(r[2]), "=r"(r[3]) : "r"(addr));
}
__device__ __forceinline__ void mma_bf16(float* d, const uint32_t* a, uint32_t b0, uint32_t b1) {
    asm volatile("mma.sync.aligned.m16n8k16.row.col.f32.bf16.bf16.f32 "
                 "{%0,%1,%2,%3}, {%4,%5,%6,%7}, {%8,%9}, {%0,%1,%2,%3};"
                 : "+f"(d[0]), "+f"(d[1]), "+f"(d[2]), "+f"(d[3])
                 : "r"(a[0]), "r"(a[1]), "r"(a[2]), "r"(a[3]), "r"(b0), "r"(b1));
}
__device__ __forceinline__ uint32_t pack2(float lo, float hi) {
    uint32_t r;
    asm("cvt.rn.bf16x2.f32 %0, %1, %2;" : "=r"(r) : "f"(hi), "f"(lo));
    return r;
}
__device__ __forceinline__ float bf16lo(float x) {
    return __bfloat162float(__float2bfloat16_rn(x));
}
__device__ __forceinline__ void split2(float f, uint16_t& h0, uint16_t& h1) {
    __nv_bfloat16 b0 = __float2bfloat16_rn(f);
    float r = f - __bfloat162float(b0);
    __nv_bfloat16 b1 = __float2bfloat16_rn(r);
    h0 = __bfloat16_as_ushort(b0);
    h1 = __bfloat16_as_ushort(b1);
}
__device__ __forceinline__ void cp16(uint32_t smem_addr, const void* gptr) {
    asm volatile("cp.async.cg.shared.global [%0], [%1], 16;"
                 :: "r"(smem_addr), "l"(gptr) : "memory");
}
__device__ __forceinline__ void cp_commit() {
    asm volatile("cp.async.commit_group;" ::: "memory");
}
__device__ __forceinline__ void cp_wait0() {
    asm volatile("cp.async.wait_group 0;" ::: "memory");
}

// ===========================================================================
// Prep 1: W transpose + 2-way bf16 split.
// ===========================================================================
__global__ __launch_bounds__(256) void transpose_split_w(
    const float* __restrict__ WQ, const float* __restrict__ WK, const float* __restrict__ WV)
{
    __shared__ float t[32][33];
    const float* W = (blockIdx.z == 0) ? WQ : (blockIdx.z == 1) ? WK : WV;
    uint16_t* out = g_wsp + blockIdx.z * (2*DIN*HD);
    const int x0 = blockIdx.x * 32, y0 = blockIdx.y * 32;
    const int tx = threadIdx.x & 31, ty = threadIdx.x >> 5;
    #pragma unroll
    for (int j = 0; j < 4; ++j)
        t[ty + j*8][tx] = W[(y0 + ty + j*8)*HD + x0 + tx];
    __syncthreads();
    #pragma unroll
    for (int j = 0; j < 4; ++j) {
        const int n = x0 + ty + j*8;
        const int k = y0 + tx;
        uint16_t h0, h1;
        split2(t[tx][ty + j*8], h0, h1);
        out[0*DIN*HD + n*DIN + k] = h0;
        out[1*DIN*HD + n*DIN + k] = h1;
    }
}

// ===========================================================================
// Prep 2: X 2-way bf16 split (streaming).
// ===========================================================================
__global__ __launch_bounds__(256) void split_x(
    const float* __restrict__ Xq, const float* __restrict__ Xk, const float* __restrict__ Xv)
{
    const int z = blockIdx.y;
    const float* X = (z == 0) ? Xq : (z == 1) ? Xk : Xv;
    const int idx = blockIdx.x * 256 + threadIdx.x;
    float4 v = ((const float4*)X)[idx];
    uint16_t a0[4], a1[4];
    split2(v.x, a0[0], a1[0]);
    split2(v.y, a0[1], a1[1]);
    split2(v.z, a0[2], a1[2]);
    split2(v.w, a0[3], a1[3]);
    uint2* out = (uint2*)g_xsp;
    const int NX4 = BATCH*LEN*DIN/4;
    out[(z*2 + 0)*NX4 + idx] = make_uint2((uint32_t)a0[0] | ((uint32_t)a0[1]<<16),
                                          (uint32_t)a0[2] | ((uint32_t)a0[3]<<16));
    out[(z*2 + 1)*NX4 + idx] = make_uint2((uint32_t)a1[0] | ((uint32_t)a1[1]<<16),
                                          (uint32_t)a1[2] | ((uint32_t)a1[3]<<16));
}

// ===========================================================================
// Projection GEMM: mma.sync bf16, 3 cross terms, cp.async double-buffered.
// Tile 128x128, 256 threads, 2 stages x 64KB = 128KB smem, 1 CTA/SM.
// ===========================================================================
#define PSTAGE 65536
#define PSM_BYTES (2*PSTAGE)

__global__ __launch_bounds__(256, 1) void proj_mma_kernel()
{
    extern __shared__ __align__(16) char sm[];   // 2 stages of [A0 A1 B0 B1] x 16KB

    const int tid = threadIdx.x;
    const int z   = blockIdx.z;
    const int n0  = blockIdx.x * 128;
    const int m0  = blockIdx.y * 128;

    const uint16_t* xsp = g_xsp + z * (2*BATCH*LEN*DIN);
    const uint16_t* wsp = g_wsp + z * (2*DIN*HD);
    uint32_t* gdst = (z == 0) ? g_qs : (z == 1) ? g_ks : g_vs;
    const float sc = (z == 0) ? 0.125f : 1.0f;

    const int w      = tid >> 5;
    const int lane   = tid & 31;
    const int warp_m = (w & 3) * 32;
    const int warp_n = (w >> 2) * 64;

    const int rA = lane & 15;
    const int hA = lane >> 4;
    const int rB = (lane & 7) | ((lane >> 4) << 3);
    const int hB = (lane >> 3) & 1;
    const uint32_t smb = smem_u32(sm);

    // per-thread cp.async coordinates (same mapping for X and W copies)
    const int cu_s   = tid >> 7;           // plane select via u = tid + i*256
    (void)cu_s;

    float acc[2][8][4];
    #pragma unroll
    for (int mf = 0; mf < 2; ++mf)
        #pragma unroll
        for (int nf = 0; nf < 8; ++nf)
            #pragma unroll
            for (int e = 0; e < 4; ++e) acc[mf][nf][e] = 0.0f;

    // prefetch helper (macro-ish lambda)
    auto prefetch = [&](int c, int st) {
        const int c64 = c * 64;
        const uint32_t sbase = smb + (uint32_t)(st * PSTAGE);
        #pragma unroll
        for (int i = 0; i < 8; ++i) {
            const int u   = tid + i*256;      // 0..2047 16B chunks
            const int s   = u >> 10;
            const int rem = u & 1023;
            const int r   = rem >> 3;
            const int c16 = rem & 7;
            const uint32_t off = (uint32_t)(s*16384 + r*128 + ((c16 ^ (r & 7)) << 4));
            cp16(sbase + off, xsp + s*(BATCH*LEN*DIN) + (m0 + r)*DIN + c64 + c16*8);
        }
        #pragma unroll
        for (int i = 0; i < 8; ++i) {
            const int u   = tid + i*256;
            const int s   = u >> 10;
            const int rem = u & 1023;
            const int r   = rem >> 3;
            const int c16 = rem & 7;
            const uint32_t off = (uint32_t)(32768 + s*16384 + r*128 + ((c16 ^ (r & 7)) << 4));
            cp16(sbase + off, wsp + s*(DIN*HD) + (n0 + r)*DIN + c64 + c16*8);
        }
        cp_commit();
    };

    prefetch(0, 0);

    for (int c = 0; c < 8; ++c) {
        cp_wait0();
        __syncthreads();
        if (c + 1 < 8) prefetch(c + 1, (c + 1) & 1);

        const uint32_t sbase = smb + (uint32_t)((c & 1) * PSTAGE);
        #pragma unroll
        for (int ks = 0; ks < 4; ++ks) {
            uint32_t a[2][2][4];
            #pragma unroll
            for (int s = 0; s < 2; ++s)
                #pragma unroll
                for (int mf = 0; mf < 2; ++mf) {
                    const uint32_t addr = sbase + s*16384
                        + (uint32_t)((warp_m + mf*16 + rA)*128)
                        + (uint32_t)((((ks*2) + hA) ^ (rA & 7)) << 4);
                    ldsm_x4(a[s][mf], addr);
                }
            #pragma unroll
            for (int bj = 0; bj < 2; ++bj) {
                uint32_t bf[4][4];
                #pragma unroll
                for (int nf2 = 0; nf2 < 4; ++nf2) {
                    const uint32_t addr = sbase + 32768 + bj*16384
                        + (uint32_t)((warp_n + nf2*16 + rB)*128)
                        + (uint32_t)((((ks*2) + hB) ^ (rB & 7)) << 4);
                    ldsm_x4(bf[nf2], addr);
                }
                #pragma unroll
                for (int ai = 0; ai < 2; ++ai) {
                    if (ai + bj > 1) break;   // terms (0,0),(0,1),(1,0)
                    #pragma unroll
                    for (int mf = 0; mf < 2; ++mf)
                        #pragma unroll
                        for (int nf = 0; nf < 8; ++nf)
                            mma_bf16(acc[mf][nf], a[ai][mf],
                                     bf[nf >> 1][(nf & 1)*2], bf[nf >> 1][(nf & 1)*2 + 1]);
                }
            }
        }
        __syncthreads();   // reads of this stage done before it is overwritten next+1 iter
    }

    // --- epilogue: split2 -> bf16 planes [s][bh][l][d] ---
    const int g  = lane >> 2;
    const int tc = lane & 3;
    #pragma unroll
    for (int mf = 0; mf < 2; ++mf)
        #pragma unroll
        for (int nf = 0; nf < 8; ++nf) {
            const int mrow = m0 + warp_m + mf*16 + g;
            const int col  = n0 + warp_n + nf*8 + tc*2;
            const int b = mrow >> 10, l = mrow & 1023;
            const int h = col >> 6,   d = col & 63;
            const int bh = b*NHEAD + h;
            #pragma unroll
            for (int half = 0; half < 2; ++half) {
                const float x0 = acc[mf][nf][half*2 + 0] * sc;
                const float x1 = acc[mf][nf][half*2 + 1] * sc;
                const uint32_t lo = pack2(x0, x1);
                const uint32_t hi = pack2(x0 - bf16lo(x0), x1 - bf16lo(x1));
                const int row = l + half*8;
                const uint32_t idx = (uint32_t)((bh*1024 + row)*32 + (d >> 1));
                gdst[idx]             = lo;
                gdst[PLANE_U32 + idx] = hi;
            }
        }
}

// ===========================================================================
// Causal flash attention: mma.sync bf16, cp.async double-buffered K/V.
// Q resident 16KB; KV stages 2 x 32KB at +16384; total 80KB.
// ===========================================================================
#define KVSTAGE 32768
#define ASM_BYTES (16384 + 2*KVSTAGE)

__global__ __launch_bounds__(128) void attn_mma_kernel(float* __restrict__ out)
{
    extern __shared__ __align__(16) char sm[];
    const uint32_t smb = smem_u32(sm);

    const int tid  = threadIdx.x;
    const int lane = tid & 31;
    const int w    = tid >> 5;
    const int bh   = blockIdx.x;                 // 0..63
    const int qt   = 15 - (int)blockIdx.y;       // heavy q-tiles first
    const int q0   = qt * 64;

    const uint16_t* qsp = (const uint16_t*)g_qs;
    const uint16_t* ksp = (const uint16_t*)g_ks;
    const uint16_t* vsp = (const uint16_t*)g_vs;
    const int PLANE_U16 = PLANE_U32 * 2;

    const int warp_m = w * 16;
    const int rA = lane & 15;
    const int hA = lane >> 4;
    const int rB = (lane & 7) | ((lane >> 4) << 3);
    const int hB = (lane >> 3) & 1;
    const int g  = lane >> 2;
    const int t4 = lane & 3;

    auto prefetch_kv = [&](int kt, int st) {
        const int k0 = kt * 64;
        const uint32_t sbase = smb + 16384u + (uint32_t)(st * KVSTAGE);
        #pragma unroll
        for (int i = 0; i < 16; ++i) {
            const int t    = tid + i*128;      // 0..2047 16B chunks
            const int tens = t >> 10;          // 0 = K, 1 = V
            const int rem  = t & 1023;
            const int s    = rem >> 9;
            const int rem2 = rem & 511;
            const int r    = rem2 >> 3;
            const int c16  = rem2 & 7;
            const uint16_t* src = (tens == 0) ? ksp : vsp;
            const uint32_t off = (uint32_t)(tens*16384 + s*8192 + r*128
                                            + ((c16 ^ (r & 7)) << 4));
            cp16(sbase + off, src + s*PLANE_U16 + ((bh*1024 + k0 + r)*64) + c16*8);
        }
        cp_commit();
    };

    prefetch_kv(0, 0);

    // ---- copy Q planes (64 rows x 128B x 2) ----
    #pragma unroll
    for (int i = 0; i < 8; ++i) {
        const int t   = tid + i*128;
        const int s   = t >> 9;
        const int rem = t & 511;
        const int r   = rem >> 3;
        const int c16 = rem & 7;
        const uint4 v = *(const uint4*)(qsp + s*PLANE_U16 + ((bh*1024 + q0 + r)*64) + c16*8);
        const uint32_t off = (uint32_t)(s*8192 + r*128 + ((c16 ^ (r & 7)) << 4));
        *(uint4*)(sm + off) = v;
    }
    __syncthreads();

    uint32_t qf[2][4][4];
    #pragma unroll
    for (int s = 0; s < 2; ++s)
        #pragma unroll
        for (int ks = 0; ks < 4; ++ks) {
            const uint32_t addr = smb + s*8192
                + (uint32_t)((warp_m + rA)*128)
                + (uint32_t)((((ks*2) + hA) ^ (rA & 7)) << 4);
            ldsm_x4(qf[s][ks], addr);
        }

    float O[8][4];
    #pragma unroll
    for (int nf = 0; nf < 8; ++nf)
        #pragma unroll
        for (int e = 0; e < 4; ++e) O[nf][e] = 0.0f;
    float m0 = -1e30f, m1 = -1e30f, l0 = 0.0f, l1 = 0.0f;

    for (int kt = 0; kt <= qt; ++kt) {
        cp_wait0();
        __syncthreads();
        if (kt < qt) prefetch_kv(kt + 1, (kt + 1) & 1);

        const uint32_t Kbase = smb + 16384u + (uint32_t)((kt & 1) * KVSTAGE);
        const uint32_t Vbase = Kbase + 16384u;

        float c[8][4];
        #pragma unroll
        for (int nf = 0; nf < 8; ++nf)
            #pragma unroll
            for (int e = 0; e < 4; ++e) c[nf][e] = 0.0f;

        #pragma unroll
        for (int ks = 0; ks < 4; ++ks) {
            uint32_t kb[2][4][4];
            #pragma unroll
            for (int s = 0; s < 2; ++s)
                #pragma unroll
                for (int nf2 = 0; nf2 < 4; ++nf2) {
                    const uint32_t addr = Kbase + s*8192
                        + (uint32_t)((nf2*16 + rB)*128)
                        + (uint32_t)((((ks*2) + hB) ^ (rB & 7)) << 4);
                    ldsm_x4(kb[s][nf2], addr);
                }
            #pragma unroll
            for (int sq = 0; sq < 2; ++sq)
                #pragma unroll
                for (int sk = 0; sk < 2; ++sk) {
                    if (sq + sk > 1) continue;   // drop q1*k1 residual product
                    #pragma unroll
                    for (int nf = 0; nf < 8; ++nf)
                        mma_bf16(c[nf], qf[sq][ks],
                                 kb[sk][nf >> 1][(nf & 1)*2], kb[sk][nf >> 1][(nf & 1)*2 + 1]);
                }
        }

        if (kt == qt) {
            #pragma unroll
            for (int nf = 0; nf < 8; ++nf) {
                const int col = nf*8 + t4*2;
                const int r0  = warp_m + g;
                const int r1  = r0 + 8;
                if (col     > r0) c[nf][0] = -1e30f;
                if (col + 1 > r0) c[nf][1] = -1e30f;
                if (col     > r1) c[nf][2] = -1e30f;
                if (col + 1 > r1) c[nf][3] = -1e30f;
            }
        }

        float mx0 = -1e30f, mx1 = -1e30f;
        #pragma unroll
        for (int nf = 0; nf < 8; ++nf) {
            mx0 = fmaxf(mx0, fmaxf(c[nf][0], c[nf][1]));
            mx1 = fmaxf(mx1, fmaxf(c[nf][2], c[nf][3]));
        }
        mx0 = fmaxf(mx0, __shfl_xor_sync(0xffffffffu, mx0, 1));
        mx0 = fmaxf(mx0, __shfl_xor_sync(0xffffffffu, mx0, 2));
        mx1 = fmaxf(mx1, __shfl_xor_sync(0xffffffffu, mx1, 1));
        mx1 = fmaxf(mx1, __shfl_xor_sync(0xffffffffu, mx1, 2));

        const float mn0 = fmaxf(m0, mx0);
        const float mn1 = fmaxf(m1, mx1);
        const float corr0 = __expf(m0 - mn0);
        const float corr1 = __expf(m1 - mn1);
        m0 = mn0; m1 = mn1;

        float s0 = 0.0f, s1 = 0.0f;
        #pragma unroll
        for (int nf = 0; nf < 8; ++nf) {
            c[nf][0] = __expf(c[nf][0] - mn0); s0 += c[nf][0];
            c[nf][1] = __expf(c[nf][1] - mn0); s0 += c[nf][1];
            c[nf][2] = __expf(c[nf][2] - mn1); s1 += c[nf][2];
            c[nf][3] = __expf(c[nf][3] - mn1); s1 += c[nf][3];
        }
        s0 += __shfl_xor_sync(0xffffffffu, s0, 1);
        s0 += __shfl_xor_sync(0xffffffffu, s0, 2);
        s1 += __shfl_xor_sync(0xffffffffu, s1, 1);
        s1 += __shfl_xor_sync(0xffffffffu, s1, 2);
        l0 = l0*corr0 + s0;
        l1 = l1*corr1 + s1;

        #pragma unroll
        for (int nf = 0; nf < 8; ++nf) {
            O[nf][0] *= corr0; O[nf][1] *= corr0;
            O[nf][2] *= corr1; O[nf][3] *= corr1;
        }

        #pragma unroll
        for (int ks2 = 0; ks2 < 4; ++ks2) {
            const float va = c[2*ks2][0],   vb_ = c[2*ks2][1],
                        vc = c[2*ks2][2],   vd = c[2*ks2][3];
            const float wa = c[2*ks2+1][0], wb = c[2*ks2+1][1],
                        wc = c[2*ks2+1][2], wd = c[2*ks2+1][3];
            uint32_t pa0[4], pa1[4];
            pa0[0] = pack2(va, vb_); pa0[1] = pack2(vc, vd);
            pa0[2] = pack2(wa, wb);  pa0[3] = pack2(wc, wd);
            pa1[0] = pack2(va - bf16lo(va), vb_ - bf16lo(vb_));
            pa1[1] = pack2(vc - bf16lo(vc), vd - bf16lo(vd));
            pa1[2] = pack2(wa - bf16lo(wa), wb - bf16lo(wb));
            pa1[3] = pack2(wc - bf16lo(wc), wd - bf16lo(wd));

            uint32_t vbf[2][4][4];
            const int keyrow = ks2*16 + (lane & 15);
            #pragma unroll
            for (int s = 0; s < 2; ++s)
                #pragma unroll
                for (int dp = 0; dp < 4; ++dp) {
                    const uint32_t addr = Vbase + s*8192
                        + (uint32_t)(keyrow*128)
                        + (uint32_t)(((dp*2 + (lane >> 4)) ^ (keyrow & 7)) << 4);
                    ldsm_x4_t(vbf[s][dp], addr);
                }
            #pragma unroll
            for (int nf = 0; nf < 8; ++nf) {
                const uint32_t b00 = vbf[0][nf >> 1][(nf & 1)*2];
                const uint32_t b01 = vbf[0][nf >> 1][(nf & 1)*2 + 1];
                const uint32_t b10 = vbf[1][nf >> 1][(nf & 1)*2];
                const uint32_t b11 = vbf[1][nf >> 1][(nf & 1)*2 + 1];
                mma_bf16(O[nf], pa0, b00, b01);
                mma_bf16(O[nf], pa1, b00, b01);
                mma_bf16(O[nf], pa0, b10, b11);
            }
        }
        __syncthreads();   // stage reads done before overwrite in next+1 iter
    }

    const float inv0 = 1.0f / l0;
    const float inv1 = 1.0f / l1;
    const int b = bh >> 3;
    const int h = bh & 7;
    const int row0 = q0 + warp_m + g;
    const int row1 = row0 + 8;
    #pragma unroll
    for (int nf = 0; nf < 8; ++nf) {
        const int d = nf*8 + t4*2;
        *(float2*)(out + (b*LEN + row0)*HD + h*HDIM + d) =
            make_float2(O[nf][0]*inv0, O[nf][1]*inv0);
        *(float2*)(out + (b*LEN + row1)*HD + h*HDIM + d) =
            make_float2(O[nf][2]*inv1, O[nf][3]*inv1);
    }
}

// ---------------------------------------------------------------------------
extern "C" void kernel_launch(void* const* d_in, const int* in_sizes, int n_in,
                              void* d_out, int out_size)
{
    (void)in_sizes; (void)n_in; (void)out_size;
    const float* Qseq = (const float*)d_in[0];
    const float* Kseq = (const float*)d_in[1];
    const float* Vseq = (const float*)d_in[2];
    const float* WQ   = (const float*)d_in[3];
    const float* WK   = (const float*)d_in[4];
    const float* WV   = (const float*)d_in[5];
    float* out = (float*)d_out;

    transpose_split_w<<<dim3(16,16,3), 256>>>(WQ, WK, WV);
    split_x<<<dim3(BATCH*LEN*DIN/4/256, 3), 256>>>(Qseq, Kseq, Vseq);

    cudaFuncSetAttribute(proj_mma_kernel, cudaFuncAttributeMaxDynamicSharedMemorySize, PSM_BYTES);
    proj_mma_kernel<<<dim3(4, 64, 3), 256, PSM_BYTES>>>();

    cudaFuncSetAttribute(attn_mma_kernel, cudaFuncAttributeMaxDynamicSharedMemorySize, ASM_BYTES);
    attn_mma_kernel<<<dim3(64, 16), 128, ASM_BYTES>>>(out);
}